// round 1
// baseline (speedup 1.0000x reference)
#include <cuda_runtime.h>
#include <math.h>
#include <stddef.h>

// Problem constants (fixed by the reference)
#define D_MODEL 1024
#define DK      1024
#define BATCH   4
#define SEQ     2048
#define BT      (BATCH * SEQ)   // 8192

// ---------------------------------------------------------------------------
// Scratch: __device__ globals (allocation-free per harness rules)
// Q,K,V: 8192x1024 fp32 each (32 MB), S: 4x2048x2048 fp32 (64 MB)
// ---------------------------------------------------------------------------
__device__ float g_Q[(size_t)BT * DK];
__device__ float g_K[(size_t)BT * DK];
__device__ float g_V[(size_t)BT * DK];
__device__ float g_S[(size_t)BATCH * SEQ * SEQ];

// ---------------------------------------------------------------------------
// SGEMM NN:  C[M,N] = A[M,K] @ B[K,N]      (row-major, all dims % 128/16 == 0)
// 128x128 block tile, BK=16, 256 threads, 8x8 per-thread microtile.
// blockIdx.z selects batch via strides.
// ---------------------------------------------------------------------------
__global__ __launch_bounds__(256)
void sgemm_nn_kernel(const float* __restrict__ A, const float* __restrict__ B,
                     float* __restrict__ C, int M, int N, int K,
                     size_t sA, size_t sB, size_t sC)
{
    A += (size_t)blockIdx.z * sA;
    B += (size_t)blockIdx.z * sB;
    C += (size_t)blockIdx.z * sC;

    const int bm = blockIdx.y * 128;
    const int bn = blockIdx.x * 128;

    __shared__ float As[16][128];
    __shared__ float Bs[16][128];

    const int tid = threadIdx.x;
    const int ty  = tid >> 4;   // 0..15
    const int tx  = tid & 15;   // 0..15

    float acc[8][8];
    #pragma unroll
    for (int i = 0; i < 8; i++)
        #pragma unroll
        for (int j = 0; j < 8; j++) acc[i][j] = 0.0f;

    for (int k0 = 0; k0 < K; k0 += 16) {
        // Load A tile: 128 rows x 16 cols = 512 float4, 2 per thread, transpose.
        #pragma unroll
        for (int i = 0; i < 2; i++) {
            int f  = tid + i * 256;
            int ar = f >> 2;              // row in tile 0..127
            int ac = (f & 3) << 2;        // col 0,4,8,12
            float4 av = *(const float4*)&A[(size_t)(bm + ar) * K + k0 + ac];
            As[ac + 0][ar] = av.x;
            As[ac + 1][ar] = av.y;
            As[ac + 2][ar] = av.z;
            As[ac + 3][ar] = av.w;
            // Load B tile: 16 rows x 128 cols = 512 float4, direct.
            int br = f >> 5;              // row 0..15
            int bc = (f & 31) << 2;       // col 0..124
            *(float4*)&Bs[br][bc] = *(const float4*)&B[(size_t)(k0 + br) * N + bn + bc];
        }
        __syncthreads();

        #pragma unroll
        for (int k = 0; k < 16; k++) {
            float a[8], b[8];
            #pragma unroll
            for (int i = 0; i < 8; i++) a[i] = As[k][ty * 8 + i];
            #pragma unroll
            for (int j = 0; j < 8; j++) b[j] = Bs[k][tx * 8 + j];
            #pragma unroll
            for (int i = 0; i < 8; i++)
                #pragma unroll
                for (int j = 0; j < 8; j++)
                    acc[i][j] = fmaf(a[i], b[j], acc[i][j]);
        }
        __syncthreads();
    }

    #pragma unroll
    for (int i = 0; i < 8; i++) {
        #pragma unroll
        for (int j = 0; j < 8; j += 4) {
            float4 v = make_float4(acc[i][j], acc[i][j + 1], acc[i][j + 2], acc[i][j + 3]);
            *(float4*)&C[(size_t)(bm + ty * 8 + i) * N + bn + tx * 8 + j] = v;
        }
    }
}

// ---------------------------------------------------------------------------
// Scores:  S[b,q,j] = scale * sum_k Q[b,q,k] * K[b,j,k]   (A @ B^T form)
// Skips fully-masked upper-triangle 128x128 blocks (softmax never reads them).
// ---------------------------------------------------------------------------
__global__ __launch_bounds__(256)
void sgemm_nt_scores_kernel(const float* __restrict__ Q, const float* __restrict__ Km,
                            float* __restrict__ S, float scale)
{
    const int b  = blockIdx.z;
    const int q0 = blockIdx.y * 128;
    const int j0 = blockIdx.x * 128;
    if (j0 > q0 + 127) return;   // entire block above diagonal -> never read

    const float* A = Q  + (size_t)b * SEQ * DK;
    const float* B = Km + (size_t)b * SEQ * DK;
    float*       C = g_S + (size_t)b * SEQ * SEQ;

    __shared__ float As[16][128];
    __shared__ float Bs[16][128];

    const int tid = threadIdx.x;
    const int ty  = tid >> 4;
    const int tx  = tid & 15;

    float acc[8][8];
    #pragma unroll
    for (int i = 0; i < 8; i++)
        #pragma unroll
        for (int j = 0; j < 8; j++) acc[i][j] = 0.0f;

    for (int k0 = 0; k0 < DK; k0 += 16) {
        #pragma unroll
        for (int i = 0; i < 2; i++) {
            int f  = tid + i * 256;
            int r  = f >> 2;
            int c  = (f & 3) << 2;
            float4 av = *(const float4*)&A[(size_t)(q0 + r) * DK + k0 + c];
            As[c + 0][r] = av.x; As[c + 1][r] = av.y;
            As[c + 2][r] = av.z; As[c + 3][r] = av.w;
            float4 bv = *(const float4*)&B[(size_t)(j0 + r) * DK + k0 + c];
            Bs[c + 0][r] = bv.x; Bs[c + 1][r] = bv.y;
            Bs[c + 2][r] = bv.z; Bs[c + 3][r] = bv.w;
        }
        __syncthreads();

        #pragma unroll
        for (int k = 0; k < 16; k++) {
            float a[8], bb[8];
            #pragma unroll
            for (int i = 0; i < 8; i++) a[i]  = As[k][ty * 8 + i];
            #pragma unroll
            for (int j = 0; j < 8; j++) bb[j] = Bs[k][tx * 8 + j];
            #pragma unroll
            for (int i = 0; i < 8; i++)
                #pragma unroll
                for (int j = 0; j < 8; j++)
                    acc[i][j] = fmaf(a[i], bb[j], acc[i][j]);
        }
        __syncthreads();
    }

    #pragma unroll
    for (int i = 0; i < 8; i++) {
        #pragma unroll
        for (int j = 0; j < 8; j += 4) {
            float4 v = make_float4(acc[i][j] * scale, acc[i][j + 1] * scale,
                                   acc[i][j + 2] * scale, acc[i][j + 3] * scale);
            *(float4*)&C[(size_t)(q0 + ty * 8 + i) * SEQ + j0 + tx * 8 + j] = v;
        }
    }
}

// ---------------------------------------------------------------------------
// Causal softmax over row (b,q): valid length q+1, zero-fill the rest.
// One block per row, 256 threads.
// ---------------------------------------------------------------------------
__global__ __launch_bounds__(256)
void softmax_causal_kernel()
{
    const int q = blockIdx.x;
    const int b = blockIdx.y;
    float* row = g_S + ((size_t)b * SEQ + q) * SEQ;
    const int len = q + 1;

    const int tid  = threadIdx.x;
    const int lane = tid & 31;
    const int w    = tid >> 5;

    __shared__ float red_max[8];
    __shared__ float red_sum[8];
    __shared__ float s_m, s_inv;

    // max
    float m = -INFINITY;
    for (int j = tid; j < len; j += 256) m = fmaxf(m, row[j]);
    #pragma unroll
    for (int o = 16; o; o >>= 1) m = fmaxf(m, __shfl_xor_sync(0xffffffffu, m, o));
    if (lane == 0) red_max[w] = m;
    __syncthreads();
    if (w == 0) {
        float v = (lane < 8) ? red_max[lane] : -INFINITY;
        #pragma unroll
        for (int o = 4; o; o >>= 1) v = fmaxf(v, __shfl_xor_sync(0xffffffffu, v, o));
        if (lane == 0) s_m = v;
    }
    __syncthreads();
    m = s_m;

    // sum of exp
    float s = 0.0f;
    for (int j = tid; j < len; j += 256) s += __expf(row[j] - m);
    #pragma unroll
    for (int o = 16; o; o >>= 1) s += __shfl_xor_sync(0xffffffffu, s, o);
    if (lane == 0) red_sum[w] = s;
    __syncthreads();
    if (w == 0) {
        float v = (lane < 8) ? red_sum[lane] : 0.0f;
        #pragma unroll
        for (int o = 4; o; o >>= 1) v += __shfl_xor_sync(0xffffffffu, v, o);
        if (lane == 0) s_inv = 1.0f / v;
    }
    __syncthreads();
    const float inv = s_inv;

    // normalize + zero-fill masked tail
    for (int j = tid; j < SEQ; j += 256)
        row[j] = (j < len) ? __expf(row[j] - m) * inv : 0.0f;
}

// ---------------------------------------------------------------------------
// Launch
// ---------------------------------------------------------------------------
extern "C" void kernel_launch(void* const* d_in, const int* in_sizes, int n_in,
                              void* d_out, int out_size)
{
    const float* x  = (const float*)d_in[0];
    const float* Wq = (const float*)d_in[1];
    const float* Wk = (const float*)d_in[2];
    const float* Wv = (const float*)d_in[3];
    float* out = (float*)d_out;

    float *Qp, *Kp, *Vp;
    cudaGetSymbolAddress((void**)&Qp, g_Q);
    cudaGetSymbolAddress((void**)&Kp, g_K);
    cudaGetSymbolAddress((void**)&Vp, g_V);

    // 1) QKV projections: (8192x1024) @ (1024x1024)
    {
        dim3 grid(DK / 128, BT / 128, 1);
        sgemm_nn_kernel<<<grid, 256>>>(x, Wq, Qp, BT, DK, D_MODEL, 0, 0, 0);
        sgemm_nn_kernel<<<grid, 256>>>(x, Wk, Kp, BT, DK, D_MODEL, 0, 0, 0);
        sgemm_nn_kernel<<<grid, 256>>>(x, Wv, Vp, BT, DK, D_MODEL, 0, 0, 0);
    }

    // 2) Scores = scale * Q @ K^T  (causal block skip)
    {
        dim3 grid(SEQ / 128, SEQ / 128, BATCH);
        sgemm_nt_scores_kernel<<<grid, 256>>>(Qp, Kp, nullptr, 1.0f / 32.0f);
    }

    // 3) Causal softmax (in place on g_S)
    {
        dim3 grid(SEQ, BATCH, 1);
        softmax_causal_kernel<<<grid, 256>>>();
    }

    // 4) out = P @ V per batch: (2048x2048) @ (2048x1024)
    {
        float* Sp;
        cudaGetSymbolAddress((void**)&Sp, g_S);
        dim3 grid(DK / 128, SEQ / 128, BATCH);
        sgemm_nn_kernel<<<grid, 256>>>(Sp, Vp, out, SEQ, DK, SEQ,
                                       (size_t)SEQ * SEQ, (size_t)SEQ * DK, (size_t)SEQ * DK);
    }
}

// round 3
// speedup vs baseline: 2.4090x; 2.4090x over previous
#include <cuda_runtime.h>
#include <cuda_bf16.h>
#include <math.h>
#include <stddef.h>
#include <stdint.h>

// Problem constants
#define D_MODEL 1024
#define DK      1024
#define BATCH   4
#define SEQ     2048
#define BT      (BATCH * SEQ)   // 8192

typedef __nv_bfloat16 bf16;

// ===========================================================================
// Scratch (__device__ globals; allocation-free)
// ===========================================================================
__device__ bf16 g_xhi[(size_t)BT * D_MODEL];
__device__ bf16 g_xlo[(size_t)BT * D_MODEL];
__device__ bf16 g_wthi[3][(size_t)D_MODEL * DK];   // W^T, (dk, d_model) K-major
__device__ bf16 g_wtlo[3][(size_t)D_MODEL * DK];
__device__ bf16 g_Qhi[(size_t)BT * DK];
__device__ bf16 g_Qlo[(size_t)BT * DK];
__device__ bf16 g_Khi[(size_t)BT * DK];
__device__ bf16 g_Klo[(size_t)BT * DK];
__device__ bf16 g_Vhi[(size_t)BT * DK];
__device__ bf16 g_Vlo[(size_t)BT * DK];
__device__ bf16 g_Vthi[(size_t)BATCH * DK * SEQ]; // per batch: (dk, t)
__device__ bf16 g_Vtlo[(size_t)BATCH * DK * SEQ];
__device__ float g_S[(size_t)BATCH * SEQ * SEQ];
__device__ bf16 g_Phi[(size_t)BATCH * SEQ * SEQ];
__device__ bf16 g_Plo[(size_t)BATCH * SEQ * SEQ];

__device__ __forceinline__ void split_f32(float v, bf16& h, bf16& l) {
    h = __float2bfloat16(v);
    l = __float2bfloat16(v - __bfloat162float(h));
}

__device__ __forceinline__ uint32_t smem_to_u32(const void* p) {
    uint32_t a;
    asm("{ .reg .u64 t; cvta.to.shared.u64 t, %1; cvt.u32.u64 %0, t; }" : "=r"(a) : "l"(p));
    return a;
}

// ldmatrix x4 (non-transposed), 32-bit shared address
__device__ __forceinline__ void ldm_x4(uint32_t& r0, uint32_t& r1, uint32_t& r2, uint32_t& r3,
                                       uint32_t addr) {
    asm volatile("ldmatrix.sync.aligned.m8n8.x4.shared.b16 {%0,%1,%2,%3}, [%4];"
                 : "=r"(r0), "=r"(r1), "=r"(r2), "=r"(r3) : "r"(addr));
}

// m16n8k16 bf16 HMMA, fp32 accum
__device__ __forceinline__ void mma_bf16(float* c, const uint32_t* a, const uint32_t* b) {
    asm volatile("mma.sync.aligned.m16n8k16.row.col.f32.bf16.bf16.f32 "
                 "{%0,%1,%2,%3}, {%4,%5,%6,%7}, {%8,%9}, {%0,%1,%2,%3};"
                 : "+f"(c[0]), "+f"(c[1]), "+f"(c[2]), "+f"(c[3])
                 : "r"(a[0]), "r"(a[1]), "r"(a[2]), "r"(a[3]), "r"(b[0]), "r"(b[1]));
}

// Swizzled SMEM address: tile layout 128 rows x 32 bf16 (64B rows, 4x16B chunks).
// chunk' = chunk ^ ((row>>1)&3)  -> 8 distinct 16B phases per 8-row ldmatrix group.
__device__ __forceinline__ uint32_t sw(uint32_t base, int row, int ch) {
    return base + row * 64 + ((ch ^ ((row >> 1) & 3)) << 4);
}

// ===========================================================================
// Elementwise split: f32 -> (hi, lo) bf16
// ===========================================================================
__global__ __launch_bounds__(256)
void split_kernel(const float* __restrict__ in, bf16* __restrict__ hi, bf16* __restrict__ lo)
{
    size_t i = ((size_t)blockIdx.x * 256 + threadIdx.x) * 4;
    float4 v = *(const float4*)(in + i);
    bf16 h0, l0, h1, l1, h2, l2, h3, l3;
    split_f32(v.x, h0, l0); split_f32(v.y, h1, l1);
    split_f32(v.z, h2, l2); split_f32(v.w, h3, l3);
    uint32_t hp0 = (uint32_t)__bfloat16_as_ushort(h0) | ((uint32_t)__bfloat16_as_ushort(h1) << 16);
    uint32_t hp1 = (uint32_t)__bfloat16_as_ushort(h2) | ((uint32_t)__bfloat16_as_ushort(h3) << 16);
    uint32_t lp0 = (uint32_t)__bfloat16_as_ushort(l0) | ((uint32_t)__bfloat16_as_ushort(l1) << 16);
    uint32_t lp1 = (uint32_t)__bfloat16_as_ushort(l2) | ((uint32_t)__bfloat16_as_ushort(l3) << 16);
    *(uint2*)(hi + i) = make_uint2(hp0, hp1);
    *(uint2*)(lo + i) = make_uint2(lp0, lp1);
}

// ===========================================================================
// W (d_model, dk) f32 -> W^T (dk, d_model) split bf16
// ===========================================================================
__global__ __launch_bounds__(256)
void wt_split_kernel(const float* __restrict__ W, bf16* __restrict__ Whi, bf16* __restrict__ Wlo)
{
    __shared__ float tile[32][33];
    int x = blockIdx.x * 32 + threadIdx.x;   // n (dk)
    int y = blockIdx.y * 32 + threadIdx.y;   // k (d_model)
    #pragma unroll
    for (int i = 0; i < 32; i += 8)
        tile[threadIdx.y + i][threadIdx.x] = W[(size_t)(y + i) * DK + x];
    __syncthreads();
    int x2 = blockIdx.y * 32 + threadIdx.x;  // k
    int y2 = blockIdx.x * 32 + threadIdx.y;  // n
    #pragma unroll
    for (int i = 0; i < 32; i += 8) {
        float v = tile[threadIdx.x][threadIdx.y + i];
        bf16 h, l; split_f32(v, h, l);
        Whi[(size_t)(y2 + i) * D_MODEL + x2] = h;
        Wlo[(size_t)(y2 + i) * D_MODEL + x2] = l;
    }
}

// ===========================================================================
// V (t, dk) split bf16 -> V^T (dk, t) split bf16, per batch
// ===========================================================================
__global__ __launch_bounds__(256)
void v_transpose_kernel(const bf16* __restrict__ Vhi, const bf16* __restrict__ Vlo,
                        bf16* __restrict__ Vthi, bf16* __restrict__ Vtlo)
{
    __shared__ bf16 th[32][34];
    __shared__ bf16 tl[32][34];
    const size_t in_base  = (size_t)blockIdx.z * SEQ * DK;
    const size_t out_base = (size_t)blockIdx.z * DK * SEQ;
    int n = blockIdx.x * 32 + threadIdx.x;   // dk
    int t = blockIdx.y * 32 + threadIdx.y;   // seq
    #pragma unroll
    for (int i = 0; i < 32; i += 8) {
        th[threadIdx.y + i][threadIdx.x] = Vhi[in_base + (size_t)(t + i) * DK + n];
        tl[threadIdx.y + i][threadIdx.x] = Vlo[in_base + (size_t)(t + i) * DK + n];
    }
    __syncthreads();
    int t2 = blockIdx.y * 32 + threadIdx.x;
    int n2 = blockIdx.x * 32 + threadIdx.y;
    #pragma unroll
    for (int i = 0; i < 32; i += 8) {
        Vthi[out_base + (size_t)(n2 + i) * SEQ + t2] = th[threadIdx.x][threadIdx.y + i];
        Vtlo[out_base + (size_t)(n2 + i) * SEQ + t2] = tl[threadIdx.x][threadIdx.y + i];
    }
}

// ===========================================================================
// HMMA split-bf16 GEMM:  C[M,N] = scale * (A @ B^T)
//   A_hi/lo, B_hi/lo: K-major rows, ld = K.
//   acc = A_hi@B_hi + A_lo@B_hi + A_hi@B_lo   (fp32 accum via mma.sync)
//   128x128 CTA tile, 8 warps (4 in M x 2 in N), warp tile 32x64.
//   mode 0: write f32 * scale; mode 1: write split bf16 (Chi, Clo)
//   causal: skip CTA if bn > bm+127;  trik: K limited to bm+128.
// ===========================================================================
__global__ __launch_bounds__(256, 2)
void gemm_nt_hmma(const bf16* __restrict__ Ahi, const bf16* __restrict__ Alo,
                  const bf16* __restrict__ Bhi, const bf16* __restrict__ Blo,
                  int K, size_t sA, size_t sB,
                  int mode, float scale, int causal, int trik,
                  float* __restrict__ Cf, int ldc, size_t sC,
                  bf16* __restrict__ Chi, bf16* __restrict__ Clo)
{
    const int bm = blockIdx.y * 128;
    const int bn = blockIdx.x * 128;
    const int b  = blockIdx.z;
    if (causal && bn > bm + 127) return;

    Ahi += (size_t)b * sA;  Alo += (size_t)b * sA;
    Bhi += (size_t)b * sB;  Blo += (size_t)b * sB;

    __shared__ bf16 sA0[128 * 32];
    __shared__ bf16 sA1[128 * 32];
    __shared__ bf16 sB0[128 * 32];
    __shared__ bf16 sB1[128 * 32];
    const uint32_t aA0 = smem_to_u32(sA0), aA1 = smem_to_u32(sA1);
    const uint32_t aB0 = smem_to_u32(sB0), aB1 = smem_to_u32(sB1);

    const int tid  = threadIdx.x;
    const int lane = tid & 31;
    const int wid  = tid >> 5;
    const int wm   = wid & 3;    // 0..3 -> 32-row slice
    const int wn   = wid >> 2;   // 0..1 -> 64-col slice

    float acc[2][8][4];
    #pragma unroll
    for (int mt = 0; mt < 2; mt++)
        #pragma unroll
        for (int nt = 0; nt < 8; nt++)
            #pragma unroll
            for (int j = 0; j < 4; j++) acc[mt][nt][j] = 0.0f;

    int Keff = trik ? (bm + 128 < K ? bm + 128 : K) : K;

    for (int k0 = 0; k0 < Keff; k0 += 32) {
        // ---- global -> swizzled smem: 4 tiles of 128x32 bf16 ----
        #pragma unroll
        for (int i = 0; i < 2; i++) {
            const int f = tid + (i << 8);
            const int r = f >> 2;
            const int c = f & 3;
            const uint32_t so = (uint32_t)(r * 64 + ((c ^ ((r >> 1) & 3)) << 4));
            const size_t ga = (size_t)(bm + r) * K + k0 + c * 8;
            const size_t gb = (size_t)(bn + r) * K + k0 + c * 8;
            *(uint4*)((char*)sA0 + so) = *(const uint4*)(Ahi + ga);
            *(uint4*)((char*)sA1 + so) = *(const uint4*)(Alo + ga);
            *(uint4*)((char*)sB0 + so) = *(const uint4*)(Bhi + gb);
            *(uint4*)((char*)sB1 + so) = *(const uint4*)(Blo + gb);
        }
        __syncthreads();

        #pragma unroll
        for (int ks = 0; ks < 2; ks++) {
            const int lrow = lane & 15;
            const int ch   = ks * 2 + (lane >> 4);

            uint32_t ah[2][4], aw[2][4], bb[8][2];

            // A_hi fragments (2 m-tiles)
            #pragma unroll
            for (int mt = 0; mt < 2; mt++) {
                const int r = wm * 32 + mt * 16 + lrow;
                ldm_x4(ah[mt][0], ah[mt][1], ah[mt][2], ah[mt][3], sw(aA0, r, ch));
            }
            // B_hi fragments (8 n-tiles via 4 x4 ldmatrix)
            #pragma unroll
            for (int np = 0; np < 4; np++) {
                const int r = wn * 64 + np * 16 + lrow;
                uint32_t r0, r1, r2, r3;
                ldm_x4(r0, r1, r2, r3, sw(aB0, r, ch));
                bb[2*np][0] = r0; bb[2*np+1][0] = r1;
                bb[2*np][1] = r2; bb[2*np+1][1] = r3;
            }
            // pass 1: A_hi @ B_hi
            #pragma unroll
            for (int mt = 0; mt < 2; mt++)
                #pragma unroll
                for (int nt = 0; nt < 8; nt++)
                    mma_bf16(acc[mt][nt], ah[mt], bb[nt]);

            // pass 2: A_lo @ B_hi
            #pragma unroll
            for (int mt = 0; mt < 2; mt++) {
                const int r = wm * 32 + mt * 16 + lrow;
                ldm_x4(aw[mt][0], aw[mt][1], aw[mt][2], aw[mt][3], sw(aA1, r, ch));
            }
            #pragma unroll
            for (int mt = 0; mt < 2; mt++)
                #pragma unroll
                for (int nt = 0; nt < 8; nt++)
                    mma_bf16(acc[mt][nt], aw[mt], bb[nt]);

            // pass 3: A_hi @ B_lo
            #pragma unroll
            for (int np = 0; np < 4; np++) {
                const int r = wn * 64 + np * 16 + lrow;
                uint32_t r0, r1, r2, r3;
                ldm_x4(r0, r1, r2, r3, sw(aB1, r, ch));
                bb[2*np][0] = r0; bb[2*np+1][0] = r1;
                bb[2*np][1] = r2; bb[2*np+1][1] = r3;
            }
            #pragma unroll
            for (int mt = 0; mt < 2; mt++)
                #pragma unroll
                for (int nt = 0; nt < 8; nt++)
                    mma_bf16(acc[mt][nt], ah[mt], bb[nt]);
        }
        __syncthreads();
    }

    // ---- epilogue ----
    const int tr = lane >> 2;          // 0..7
    const int tc = (lane & 3) * 2;     // 0,2,4,6
    if (mode == 0) {
        float* Cb = Cf + (size_t)b * sC;
        #pragma unroll
        for (int mt = 0; mt < 2; mt++) {
            #pragma unroll
            for (int nt = 0; nt < 8; nt++) {
                const int row = bm + wm * 32 + mt * 16 + tr;
                const int col = bn + wn * 64 + nt * 8 + tc;
                float2 v0 = make_float2(acc[mt][nt][0] * scale, acc[mt][nt][1] * scale);
                float2 v1 = make_float2(acc[mt][nt][2] * scale, acc[mt][nt][3] * scale);
                *(float2*)&Cb[(size_t)row * ldc + col]       = v0;
                *(float2*)&Cb[(size_t)(row + 8) * ldc + col] = v1;
            }
        }
    } else {
        #pragma unroll
        for (int mt = 0; mt < 2; mt++) {
            #pragma unroll
            for (int nt = 0; nt < 8; nt++) {
                const int row = bm + wm * 32 + mt * 16 + tr;
                const int col = bn + wn * 64 + nt * 8 + tc;
                #pragma unroll
                for (int h = 0; h < 2; h++) {
                    float v0 = acc[mt][nt][2*h + 0] * scale;
                    float v1 = acc[mt][nt][2*h + 1] * scale;
                    bf16 h0, l0, h1, l1;
                    split_f32(v0, h0, l0); split_f32(v1, h1, l1);
                    uint32_t hp = (uint32_t)__bfloat16_as_ushort(h0) |
                                  ((uint32_t)__bfloat16_as_ushort(h1) << 16);
                    uint32_t lp = (uint32_t)__bfloat16_as_ushort(l0) |
                                  ((uint32_t)__bfloat16_as_ushort(l1) << 16);
                    *(uint32_t*)&Chi[(size_t)(row + 8*h) * ldc + col] = hp;
                    *(uint32_t*)&Clo[(size_t)(row + 8*h) * ldc + col] = lp;
                }
            }
        }
    }
}

// ===========================================================================
// Causal softmax: reads g_S f32 row, writes P directly as split bf16 (+zero tail)
// ===========================================================================
__global__ __launch_bounds__(256)
void softmax_causal_kernel()
{
    const int q = blockIdx.x;
    const int b = blockIdx.y;
    const size_t base = ((size_t)b * SEQ + q) * SEQ;
    const float* row = g_S + base;
    const int len = q + 1;

    const int tid = threadIdx.x, lane = tid & 31, w = tid >> 5;
    __shared__ float red_max[8], red_sum[8], s_m, s_inv;

    float m = -INFINITY;
    for (int j = tid; j < len; j += 256) m = fmaxf(m, row[j]);
    #pragma unroll
    for (int o = 16; o; o >>= 1) m = fmaxf(m, __shfl_xor_sync(0xffffffffu, m, o));
    if (lane == 0) red_max[w] = m;
    __syncthreads();
    if (w == 0) {
        float v = (lane < 8) ? red_max[lane] : -INFINITY;
        #pragma unroll
        for (int o = 4; o; o >>= 1) v = fmaxf(v, __shfl_xor_sync(0xffffffffu, v, o));
        if (lane == 0) s_m = v;
    }
    __syncthreads();
    m = s_m;

    float s = 0.0f;
    for (int j = tid; j < len; j += 256) s += __expf(row[j] - m);
    #pragma unroll
    for (int o = 16; o; o >>= 1) s += __shfl_xor_sync(0xffffffffu, s, o);
    if (lane == 0) red_sum[w] = s;
    __syncthreads();
    if (w == 0) {
        float v = (lane < 8) ? red_sum[lane] : 0.0f;
        #pragma unroll
        for (int o = 4; o; o >>= 1) v += __shfl_xor_sync(0xffffffffu, v, o);
        if (lane == 0) s_inv = 1.0f / v;
    }
    __syncthreads();
    const float inv = s_inv;

    for (int j = tid; j < SEQ; j += 256) {
        float p = (j < len) ? __expf(row[j] - m) * inv : 0.0f;
        bf16 h, l; split_f32(p, h, l);
        g_Phi[base + j] = h;
        g_Plo[base + j] = l;
    }
}

// ===========================================================================
// Launch
// ===========================================================================
extern "C" void kernel_launch(void* const* d_in, const int* in_sizes, int n_in,
                              void* d_out, int out_size)
{
    const float* x  = (const float*)d_in[0];
    const float* Wq = (const float*)d_in[1];
    const float* Wk = (const float*)d_in[2];
    const float* Wv = (const float*)d_in[3];
    float* out = (float*)d_out;

    bf16 *xhi, *xlo, *wthi, *wtlo, *Qhi, *Qlo, *Khi, *Klo, *Vhi, *Vlo, *Vthi, *Vtlo, *Phi, *Plo;
    float *Sp;
    cudaGetSymbolAddress((void**)&xhi, g_xhi);  cudaGetSymbolAddress((void**)&xlo, g_xlo);
    cudaGetSymbolAddress((void**)&wthi, g_wthi); cudaGetSymbolAddress((void**)&wtlo, g_wtlo);
    cudaGetSymbolAddress((void**)&Qhi, g_Qhi);  cudaGetSymbolAddress((void**)&Qlo, g_Qlo);
    cudaGetSymbolAddress((void**)&Khi, g_Khi);  cudaGetSymbolAddress((void**)&Klo, g_Klo);
    cudaGetSymbolAddress((void**)&Vhi, g_Vhi);  cudaGetSymbolAddress((void**)&Vlo, g_Vlo);
    cudaGetSymbolAddress((void**)&Vthi, g_Vthi); cudaGetSymbolAddress((void**)&Vtlo, g_Vtlo);
    cudaGetSymbolAddress((void**)&Phi, g_Phi);  cudaGetSymbolAddress((void**)&Plo, g_Plo);
    cudaGetSymbolAddress((void**)&Sp, g_S);

    const size_t WSZ = (size_t)D_MODEL * DK;

    // 1) input splits / transposes
    split_kernel<<<(BT * D_MODEL) / (256 * 4), 256>>>(x, xhi, xlo);
    {
        dim3 g(DK / 32, D_MODEL / 32), blk(32, 8);
        wt_split_kernel<<<g, blk>>>(Wq, wthi + 0 * WSZ, wtlo + 0 * WSZ);
        wt_split_kernel<<<g, blk>>>(Wk, wthi + 1 * WSZ, wtlo + 1 * WSZ);
        wt_split_kernel<<<g, blk>>>(Wv, wthi + 2 * WSZ, wtlo + 2 * WSZ);
    }

    // 2) projections: Q/K/V = x @ W (as x @ (W^T)^T), split-bf16 output
    {
        dim3 grid(DK / 128, BT / 128, 1);
        gemm_nt_hmma<<<grid, 256>>>(xhi, xlo, wthi + 0 * WSZ, wtlo + 0 * WSZ,
            D_MODEL, 0, 0, 1, 1.0f, 0, 0, nullptr, DK, 0, Qhi, Qlo);
        gemm_nt_hmma<<<grid, 256>>>(xhi, xlo, wthi + 1 * WSZ, wtlo + 1 * WSZ,
            D_MODEL, 0, 0, 1, 1.0f, 0, 0, nullptr, DK, 0, Khi, Klo);
        gemm_nt_hmma<<<grid, 256>>>(xhi, xlo, wthi + 2 * WSZ, wtlo + 2 * WSZ,
            D_MODEL, 0, 0, 1, 1.0f, 0, 0, nullptr, DK, 0, Vhi, Vlo);
    }

    // 3) V transpose per batch: (t, dk) -> (dk, t)
    {
        dim3 g(DK / 32, SEQ / 32, BATCH), blk(32, 8);
        v_transpose_kernel<<<g, blk>>>(Vhi, Vlo, Vthi, Vtlo);
    }

    // 4) scores = (1/32) * Q @ K^T, causal block skip
    {
        dim3 grid(SEQ / 128, SEQ / 128, BATCH);
        gemm_nt_hmma<<<grid, 256>>>(Qhi, Qlo, Khi, Klo,
            DK, (size_t)SEQ * DK, (size_t)SEQ * DK, 0, 1.0f / 32.0f, 1, 0,
            Sp, SEQ, (size_t)SEQ * SEQ, nullptr, nullptr);
    }

    // 5) causal softmax -> split bf16 P (zero tail)
    softmax_causal_kernel<<<dim3(SEQ, BATCH), 256>>>();

    // 6) out = P @ V  (= P @ (V^T)^T), K truncated per diagonal
    {
        dim3 grid(DK / 128, SEQ / 128, BATCH);
        gemm_nt_hmma<<<grid, 256>>>(Phi, Plo, Vthi, Vtlo,
            SEQ, (size_t)SEQ * SEQ, (size_t)DK * SEQ, 0, 1.0f, 0, 1,
            out, DK, (size_t)SEQ * DK, nullptr, nullptr);
    }
}

// round 4
// speedup vs baseline: 3.1045x; 1.2887x over previous
#include <cuda_runtime.h>
#include <cuda_bf16.h>
#include <math.h>
#include <stddef.h>
#include <stdint.h>

// Problem constants
#define D_MODEL 1024
#define DK      1024
#define BATCH   4
#define SEQ     2048
#define BT      (BATCH * SEQ)   // 8192

typedef __nv_bfloat16 bf16;

// ===========================================================================
// Scratch (__device__ globals; allocation-free)
// ===========================================================================
__device__ bf16 g_xhi[(size_t)BT * D_MODEL];
__device__ bf16 g_xlo[(size_t)BT * D_MODEL];
__device__ bf16 g_wthi[3][(size_t)D_MODEL * DK];   // W^T, (dk, d_model) K-major
__device__ bf16 g_wtlo[3][(size_t)D_MODEL * DK];
__device__ bf16 g_QKVhi[3][(size_t)BT * DK];       // [0]=Q, [1]=K, [2]=V
__device__ bf16 g_QKVlo[3][(size_t)BT * DK];
__device__ bf16 g_Vthi[(size_t)BATCH * DK * SEQ];  // per batch: (dk, t)
__device__ bf16 g_Vtlo[(size_t)BATCH * DK * SEQ];
__device__ float g_S[(size_t)BATCH * SEQ * SEQ];
__device__ bf16 g_Phi[(size_t)BATCH * SEQ * SEQ];
__device__ bf16 g_Plo[(size_t)BATCH * SEQ * SEQ];

__device__ __forceinline__ void split_f32(float v, bf16& h, bf16& l) {
    h = __float2bfloat16(v);
    l = __float2bfloat16(v - __bfloat162float(h));
}

__device__ __forceinline__ uint32_t smem_to_u32(const void* p) {
    uint32_t a;
    asm("{ .reg .u64 t; cvta.to.shared.u64 t, %1; cvt.u32.u64 %0, t; }" : "=r"(a) : "l"(p));
    return a;
}

// ldmatrix x4 (non-transposed), 32-bit shared address
__device__ __forceinline__ void ldm_x4(uint32_t& r0, uint32_t& r1, uint32_t& r2, uint32_t& r3,
                                       uint32_t addr) {
    asm volatile("ldmatrix.sync.aligned.m8n8.x4.shared.b16 {%0,%1,%2,%3}, [%4];"
                 : "=r"(r0), "=r"(r1), "=r"(r2), "=r"(r3) : "r"(addr));
}

// m16n8k16 bf16 HMMA, fp32 accum
__device__ __forceinline__ void mma_bf16(float* c, const uint32_t* a, const uint32_t* b) {
    asm volatile("mma.sync.aligned.m16n8k16.row.col.f32.bf16.bf16.f32 "
                 "{%0,%1,%2,%3}, {%4,%5,%6,%7}, {%8,%9}, {%0,%1,%2,%3};"
                 : "+f"(c[0]), "+f"(c[1]), "+f"(c[2]), "+f"(c[3])
                 : "r"(a[0]), "r"(a[1]), "r"(a[2]), "r"(a[3]), "r"(b[0]), "r"(b[1]));
}

// cp.async 16B (LDGSTS)
#define CP_ASYNC16(dst, src) \
    asm volatile("cp.async.cg.shared.global [%0], [%1], 16;" :: "r"(dst), "l"(src) : "memory")
#define CP_COMMIT() asm volatile("cp.async.commit_group;" ::: "memory")
#define CP_WAIT0()  asm volatile("cp.async.wait_group 0;" ::: "memory")
#define CP_WAIT1()  asm volatile("cp.async.wait_group 1;" ::: "memory")

// Swizzled SMEM address: tile 128 rows x 32 bf16 (64B rows, 4x16B chunks).
// chunk' = chunk ^ ((row>>1)&3)  -> conflict-free ldmatrix.x4 phases.
__device__ __forceinline__ uint32_t sw(uint32_t base, int row, int ch) {
    return base + row * 64 + ((ch ^ ((row >> 1) & 3)) << 4);
}

// ===========================================================================
// Elementwise split: f32 -> (hi, lo) bf16
// ===========================================================================
__global__ __launch_bounds__(256)
void split_kernel(const float* __restrict__ in, bf16* __restrict__ hi, bf16* __restrict__ lo)
{
    size_t i = ((size_t)blockIdx.x * 256 + threadIdx.x) * 4;
    float4 v = *(const float4*)(in + i);
    bf16 h0, l0, h1, l1, h2, l2, h3, l3;
    split_f32(v.x, h0, l0); split_f32(v.y, h1, l1);
    split_f32(v.z, h2, l2); split_f32(v.w, h3, l3);
    uint32_t hp0 = (uint32_t)__bfloat16_as_ushort(h0) | ((uint32_t)__bfloat16_as_ushort(h1) << 16);
    uint32_t hp1 = (uint32_t)__bfloat16_as_ushort(h2) | ((uint32_t)__bfloat16_as_ushort(h3) << 16);
    uint32_t lp0 = (uint32_t)__bfloat16_as_ushort(l0) | ((uint32_t)__bfloat16_as_ushort(l1) << 16);
    uint32_t lp1 = (uint32_t)__bfloat16_as_ushort(l2) | ((uint32_t)__bfloat16_as_ushort(l3) << 16);
    *(uint2*)(hi + i) = make_uint2(hp0, hp1);
    *(uint2*)(lo + i) = make_uint2(lp0, lp1);
}

// ===========================================================================
// W (d_model, dk) f32 -> W^T (dk, d_model) split bf16
// ===========================================================================
__global__ __launch_bounds__(256)
void wt_split_kernel(const float* __restrict__ W, bf16* __restrict__ Whi, bf16* __restrict__ Wlo)
{
    __shared__ float tile[32][33];
    int x = blockIdx.x * 32 + threadIdx.x;   // n (dk)
    int y = blockIdx.y * 32 + threadIdx.y;   // k (d_model)
    #pragma unroll
    for (int i = 0; i < 32; i += 8)
        tile[threadIdx.y + i][threadIdx.x] = W[(size_t)(y + i) * DK + x];
    __syncthreads();
    int x2 = blockIdx.y * 32 + threadIdx.x;  // k
    int y2 = blockIdx.x * 32 + threadIdx.y;  // n
    #pragma unroll
    for (int i = 0; i < 32; i += 8) {
        float v = tile[threadIdx.x][threadIdx.y + i];
        bf16 h, l; split_f32(v, h, l);
        Whi[(size_t)(y2 + i) * D_MODEL + x2] = h;
        Wlo[(size_t)(y2 + i) * D_MODEL + x2] = l;
    }
}

// ===========================================================================
// V (t, dk) split bf16 -> V^T (dk, t) split bf16, per batch
// ===========================================================================
__global__ __launch_bounds__(256)
void v_transpose_kernel(const bf16* __restrict__ Vhi, const bf16* __restrict__ Vlo,
                        bf16* __restrict__ Vthi, bf16* __restrict__ Vtlo)
{
    __shared__ bf16 th[32][34];
    __shared__ bf16 tl[32][34];
    const size_t in_base  = (size_t)blockIdx.z * SEQ * DK;
    const size_t out_base = (size_t)blockIdx.z * DK * SEQ;
    int n = blockIdx.x * 32 + threadIdx.x;   // dk
    int t = blockIdx.y * 32 + threadIdx.y;   // seq
    #pragma unroll
    for (int i = 0; i < 32; i += 8) {
        th[threadIdx.y + i][threadIdx.x] = Vhi[in_base + (size_t)(t + i) * DK + n];
        tl[threadIdx.y + i][threadIdx.x] = Vlo[in_base + (size_t)(t + i) * DK + n];
    }
    __syncthreads();
    int t2 = blockIdx.y * 32 + threadIdx.x;
    int n2 = blockIdx.x * 32 + threadIdx.y;
    #pragma unroll
    for (int i = 0; i < 32; i += 8) {
        Vthi[out_base + (size_t)(n2 + i) * SEQ + t2] = th[threadIdx.x][threadIdx.y + i];
        Vtlo[out_base + (size_t)(n2 + i) * SEQ + t2] = tl[threadIdx.x][threadIdx.y + i];
    }
}

// ===========================================================================
// HMMA split-bf16 GEMM with cp.async double buffering
//   C[M,N] = scale * (A @ B^T); acc = Ah@Bh + Al@Bh + Ah@Bl
//   128x128 CTA tile, 8 warps (4xM, 2xN), warp tile 32x64, KC=32.
//   Dynamic SMEM: 2 stages x 32KB (A_hi, A_lo, B_hi, B_lo tiles of 128x32).
//   mode 0: f32 out * scale; mode 1: split bf16 out (Chi/Clo + z*sCbf)
//   causal: skip CTA if bn > bm+127;  trik: K limited to bm+128.
// ===========================================================================
#define STG_B   32768   // bytes per stage
#define T_A0    0
#define T_A1    8192
#define T_B0    16384
#define T_B1    24576
#define GEMM_SMEM (2 * STG_B)

__device__ __forceinline__ void load_stage(uint32_t st,
    const bf16* Ahi, const bf16* Alo, const bf16* Bhi, const bf16* Blo,
    int K, int bm, int bn, int k0, int tid)
{
    #pragma unroll
    for (int i = 0; i < 2; i++) {
        const int f = tid + (i << 8);
        const int r = f >> 2;
        const int c = f & 3;
        const uint32_t so = (uint32_t)(r * 64 + ((c ^ ((r >> 1) & 3)) << 4));
        const size_t ga = (size_t)(bm + r) * K + k0 + c * 8;
        const size_t gb = (size_t)(bn + r) * K + k0 + c * 8;
        CP_ASYNC16(st + T_A0 + so, Ahi + ga);
        CP_ASYNC16(st + T_A1 + so, Alo + ga);
        CP_ASYNC16(st + T_B0 + so, Bhi + gb);
        CP_ASYNC16(st + T_B1 + so, Blo + gb);
    }
}

__global__ __launch_bounds__(256, 2)
void gemm_nt_hmma(const bf16* __restrict__ Ahi, const bf16* __restrict__ Alo,
                  const bf16* __restrict__ Bhi, const bf16* __restrict__ Blo,
                  int K, size_t sA, size_t sB,
                  int mode, float scale, int causal, int trik,
                  float* __restrict__ Cf, int ldc, size_t sC,
                  bf16* __restrict__ Chi, bf16* __restrict__ Clo, size_t sCbf)
{
    const int bm = blockIdx.y * 128;
    const int bn = blockIdx.x * 128;
    const int b  = blockIdx.z;
    if (causal && bn > bm + 127) return;

    Ahi += (size_t)b * sA;  Alo += (size_t)b * sA;
    Bhi += (size_t)b * sB;  Blo += (size_t)b * sB;

    extern __shared__ char smem[];
    const uint32_t sb = smem_to_u32(smem);

    const int tid  = threadIdx.x;
    const int lane = tid & 31;
    const int wid  = tid >> 5;
    const int wm   = wid & 3;    // 0..3 -> 32-row slice
    const int wn   = wid >> 2;   // 0..1 -> 64-col slice

    float acc[2][8][4];
    #pragma unroll
    for (int mt = 0; mt < 2; mt++)
        #pragma unroll
        for (int nt = 0; nt < 8; nt++)
            #pragma unroll
            for (int j = 0; j < 4; j++) acc[mt][nt][j] = 0.0f;

    int Keff = trik ? (bm + 128 < K ? bm + 128 : K) : K;
    const int nc = Keff >> 5;   // Keff / 32 (Keff always a multiple of 128)

    // prologue: stage 0
    load_stage(sb, Ahi, Alo, Bhi, Blo, K, bm, bn, 0, tid);
    CP_COMMIT();

    for (int c = 0; c < nc; c++) {
        if (c + 1 < nc) {
            load_stage(sb + ((c + 1) & 1) * STG_B, Ahi, Alo, Bhi, Blo,
                       K, bm, bn, (c + 1) << 5, tid);
            CP_COMMIT();
            CP_WAIT1();
        } else {
            CP_WAIT0();
        }
        __syncthreads();

        const uint32_t st  = sb + (c & 1) * STG_B;
        const uint32_t aA0 = st + T_A0, aA1 = st + T_A1;
        const uint32_t aB0 = st + T_B0, aB1 = st + T_B1;

        #pragma unroll
        for (int ks = 0; ks < 2; ks++) {
            const int lrow = lane & 15;
            const int ch   = ks * 2 + (lane >> 4);

            uint32_t ah[2][4], aw[2][4], bb[8][2];

            #pragma unroll
            for (int mt = 0; mt < 2; mt++) {
                const int r = wm * 32 + mt * 16 + lrow;
                ldm_x4(ah[mt][0], ah[mt][1], ah[mt][2], ah[mt][3], sw(aA0, r, ch));
            }
            #pragma unroll
            for (int np = 0; np < 4; np++) {
                const int r = wn * 64 + np * 16 + lrow;
                uint32_t r0, r1, r2, r3;
                ldm_x4(r0, r1, r2, r3, sw(aB0, r, ch));
                bb[2*np][0] = r0; bb[2*np+1][0] = r1;
                bb[2*np][1] = r2; bb[2*np+1][1] = r3;
            }
            // pass 1: A_hi @ B_hi
            #pragma unroll
            for (int mt = 0; mt < 2; mt++)
                #pragma unroll
                for (int nt = 0; nt < 8; nt++)
                    mma_bf16(acc[mt][nt], ah[mt], bb[nt]);

            // pass 2: A_lo @ B_hi
            #pragma unroll
            for (int mt = 0; mt < 2; mt++) {
                const int r = wm * 32 + mt * 16 + lrow;
                ldm_x4(aw[mt][0], aw[mt][1], aw[mt][2], aw[mt][3], sw(aA1, r, ch));
            }
            #pragma unroll
            for (int mt = 0; mt < 2; mt++)
                #pragma unroll
                for (int nt = 0; nt < 8; nt++)
                    mma_bf16(acc[mt][nt], aw[mt], bb[nt]);

            // pass 3: A_hi @ B_lo
            #pragma unroll
            for (int np = 0; np < 4; np++) {
                const int r = wn * 64 + np * 16 + lrow;
                uint32_t r0, r1, r2, r3;
                ldm_x4(r0, r1, r2, r3, sw(aB1, r, ch));
                bb[2*np][0] = r0; bb[2*np+1][0] = r1;
                bb[2*np][1] = r2; bb[2*np+1][1] = r3;
            }
            #pragma unroll
            for (int mt = 0; mt < 2; mt++)
                #pragma unroll
                for (int nt = 0; nt < 8; nt++)
                    mma_bf16(acc[mt][nt], ah[mt], bb[nt]);
        }
        __syncthreads();
    }

    // ---- epilogue ----
    const int tr = lane >> 2;          // 0..7
    const int tc = (lane & 3) * 2;     // 0,2,4,6
    if (mode == 0) {
        float* Cb = Cf + (size_t)b * sC;
        #pragma unroll
        for (int mt = 0; mt < 2; mt++) {
            #pragma unroll
            for (int nt = 0; nt < 8; nt++) {
                const int row = bm + wm * 32 + mt * 16 + tr;
                const int col = bn + wn * 64 + nt * 8 + tc;
                float2 v0 = make_float2(acc[mt][nt][0] * scale, acc[mt][nt][1] * scale);
                float2 v1 = make_float2(acc[mt][nt][2] * scale, acc[mt][nt][3] * scale);
                *(float2*)&Cb[(size_t)row * ldc + col]       = v0;
                *(float2*)&Cb[(size_t)(row + 8) * ldc + col] = v1;
            }
        }
    } else {
        bf16* Hb = Chi + (size_t)b * sCbf;
        bf16* Lb = Clo + (size_t)b * sCbf;
        #pragma unroll
        for (int mt = 0; mt < 2; mt++) {
            #pragma unroll
            for (int nt = 0; nt < 8; nt++) {
                const int row = bm + wm * 32 + mt * 16 + tr;
                const int col = bn + wn * 64 + nt * 8 + tc;
                #pragma unroll
                for (int h = 0; h < 2; h++) {
                    float v0 = acc[mt][nt][2*h + 0] * scale;
                    float v1 = acc[mt][nt][2*h + 1] * scale;
                    bf16 h0, l0, h1, l1;
                    split_f32(v0, h0, l0); split_f32(v1, h1, l1);
                    uint32_t hp = (uint32_t)__bfloat16_as_ushort(h0) |
                                  ((uint32_t)__bfloat16_as_ushort(h1) << 16);
                    uint32_t lp = (uint32_t)__bfloat16_as_ushort(l0) |
                                  ((uint32_t)__bfloat16_as_ushort(l1) << 16);
                    *(uint32_t*)&Hb[(size_t)(row + 8*h) * ldc + col] = hp;
                    *(uint32_t*)&Lb[(size_t)(row + 8*h) * ldc + col] = lp;
                }
            }
        }
    }
}

// ===========================================================================
// Causal softmax: reads g_S f32 row, writes P directly as split bf16 (+zero tail)
// ===========================================================================
__global__ __launch_bounds__(256)
void softmax_causal_kernel()
{
    const int q = blockIdx.x;
    const int b = blockIdx.y;
    const size_t base = ((size_t)b * SEQ + q) * SEQ;
    const float* row = g_S + base;
    const int len = q + 1;

    const int tid = threadIdx.x, lane = tid & 31, w = tid >> 5;
    __shared__ float red_max[8], red_sum[8], s_m, s_inv;

    float m = -INFINITY;
    for (int j = tid; j < len; j += 256) m = fmaxf(m, row[j]);
    #pragma unroll
    for (int o = 16; o; o >>= 1) m = fmaxf(m, __shfl_xor_sync(0xffffffffu, m, o));
    if (lane == 0) red_max[w] = m;
    __syncthreads();
    if (w == 0) {
        float v = (lane < 8) ? red_max[lane] : -INFINITY;
        #pragma unroll
        for (int o = 4; o; o >>= 1) v = fmaxf(v, __shfl_xor_sync(0xffffffffu, v, o));
        if (lane == 0) s_m = v;
    }
    __syncthreads();
    m = s_m;

    float s = 0.0f;
    for (int j = tid; j < len; j += 256) s += __expf(row[j] - m);
    #pragma unroll
    for (int o = 16; o; o >>= 1) s += __shfl_xor_sync(0xffffffffu, s, o);
    if (lane == 0) red_sum[w] = s;
    __syncthreads();
    if (w == 0) {
        float v = (lane < 8) ? red_sum[lane] : 0.0f;
        #pragma unroll
        for (int o = 4; o; o >>= 1) v += __shfl_xor_sync(0xffffffffu, v, o);
        if (lane == 0) s_inv = 1.0f / v;
    }
    __syncthreads();
    const float inv = s_inv;

    for (int j = tid; j < SEQ; j += 256) {
        float p = (j < len) ? __expf(row[j] - m) * inv : 0.0f;
        bf16 h, l; split_f32(p, h, l);
        g_Phi[base + j] = h;
        g_Plo[base + j] = l;
    }
}

// ===========================================================================
// Launch
// ===========================================================================
extern "C" void kernel_launch(void* const* d_in, const int* in_sizes, int n_in,
                              void* d_out, int out_size)
{
    const float* x  = (const float*)d_in[0];
    const float* Wq = (const float*)d_in[1];
    const float* Wk = (const float*)d_in[2];
    const float* Wv = (const float*)d_in[3];
    float* out = (float*)d_out;

    static int attr_set = 0;
    cudaFuncSetAttribute(gemm_nt_hmma, cudaFuncAttributeMaxDynamicSharedMemorySize, GEMM_SMEM);
    (void)attr_set;

    bf16 *xhi, *xlo, *wthi, *wtlo, *qkvhi, *qkvlo, *Vthi, *Vtlo, *Phi, *Plo;
    float *Sp;
    cudaGetSymbolAddress((void**)&xhi, g_xhi);    cudaGetSymbolAddress((void**)&xlo, g_xlo);
    cudaGetSymbolAddress((void**)&wthi, g_wthi);  cudaGetSymbolAddress((void**)&wtlo, g_wtlo);
    cudaGetSymbolAddress((void**)&qkvhi, g_QKVhi); cudaGetSymbolAddress((void**)&qkvlo, g_QKVlo);
    cudaGetSymbolAddress((void**)&Vthi, g_Vthi);  cudaGetSymbolAddress((void**)&Vtlo, g_Vtlo);
    cudaGetSymbolAddress((void**)&Phi, g_Phi);    cudaGetSymbolAddress((void**)&Plo, g_Plo);
    cudaGetSymbolAddress((void**)&Sp, g_S);

    const size_t WSZ  = (size_t)D_MODEL * DK;
    const size_t QKVS = (size_t)BT * DK;

    // 1) input splits / transposes
    split_kernel<<<(BT * D_MODEL) / (256 * 4), 256>>>(x, xhi, xlo);
    {
        dim3 g(DK / 32, D_MODEL / 32), blk(32, 8);
        wt_split_kernel<<<g, blk>>>(Wq, wthi + 0 * WSZ, wtlo + 0 * WSZ);
        wt_split_kernel<<<g, blk>>>(Wk, wthi + 1 * WSZ, wtlo + 1 * WSZ);
        wt_split_kernel<<<g, blk>>>(Wv, wthi + 2 * WSZ, wtlo + 2 * WSZ);
    }

    // 2) merged QKV projection: z in {0,1,2} selects W and output slice
    {
        dim3 grid(DK / 128, BT / 128, 3);
        gemm_nt_hmma<<<grid, 256, GEMM_SMEM>>>(xhi, xlo, wthi, wtlo,
            D_MODEL, 0, WSZ, 1, 1.0f, 0, 0,
            nullptr, DK, 0, qkvhi, qkvlo, QKVS);
    }

    // 3) V transpose per batch: (t, dk) -> (dk, t)
    {
        dim3 g(DK / 32, SEQ / 32, BATCH), blk(32, 8);
        v_transpose_kernel<<<g, blk>>>(qkvhi + 2 * QKVS, qkvlo + 2 * QKVS, Vthi, Vtlo);
    }

    // 4) scores = (1/32) * Q @ K^T, causal block skip
    {
        dim3 grid(SEQ / 128, SEQ / 128, BATCH);
        gemm_nt_hmma<<<grid, 256, GEMM_SMEM>>>(qkvhi, qkvlo, qkvhi + QKVS, qkvlo + QKVS,
            DK, (size_t)SEQ * DK, (size_t)SEQ * DK, 0, 1.0f / 32.0f, 1, 0,
            Sp, SEQ, (size_t)SEQ * SEQ, nullptr, nullptr, 0);
    }

    // 5) causal softmax -> split bf16 P (zero tail)
    softmax_causal_kernel<<<dim3(SEQ, BATCH), 256>>>();

    // 6) out = P @ V  (= P @ (V^T)^T), K truncated per diagonal
    {
        dim3 grid(DK / 128, SEQ / 128, BATCH);
        gemm_nt_hmma<<<grid, 256, GEMM_SMEM>>>(Phi, Plo, Vthi, Vtlo,
            SEQ, (size_t)SEQ * SEQ, (size_t)DK * SEQ, 0, 1.0f, 0, 1,
            out, DK, (size_t)SEQ * DK, nullptr, nullptr, 0);
    }
}